// round 7
// baseline (speedup 1.0000x reference)
#include <cuda_runtime.h>
#include <math.h>

// Problem constants
constexpr int BSZ = 64;     // batch
constexpr int SEQ = 512;    // sequence length
constexpr int IN  = 512;    // input dim
constexpr int HD  = 1024;   // hidden dim
constexpr int G4  = 4 * HD; // 4096 gate columns

constexpr int NCTAS = 128;  // persistent grid (1 CTA per SM)
constexpr int NTHR  = 128;

// Scratch: xg = x @ Xcat + bcat, layout [m = b*SEQ + t][gate*HD + j]
__device__ float g_xg[(size_t)BSZ * SEQ * G4];   // 512 MB
__device__ float g_h[BSZ * HD];
__device__ unsigned g_arrive[NCTAS * 32];        // 1 flag per CTA, 128B apart
__device__ unsigned g_phase;

// Dynamic SMEM layout (floats):
//   Bs: [1024][32]  @ 0        (131072 B)  -- Hcat slice, gate-interleaved
//   As: [2][64][68] @ 32768 f  (34816 B)   -- double-buffered h chunks, dup'd {v,v}
constexpr int AS_STRIDE = 68;
constexpr int AS_BUF    = 64 * AS_STRIDE;
constexpr int F_BS = 0;
constexpr int F_AS = 32768;
constexpr int SMEM_TOTAL = (F_AS + 2 * AS_BUF) * 4;   // 165888 B

#define FMA2(acc, a, b) asm("fma.rn.f32x2 %0,%1,%2,%0;" : "+l"(acc) : "l"(a), "l"(b))

// ---------------------------------------------------------------------------
// Zero h and barrier state
// ---------------------------------------------------------------------------
__global__ void init_state_kernel() {
    int i = blockIdx.x * blockDim.x + threadIdx.x;
    if (i < BSZ * HD) g_h[i] = 0.0f;
    if (i < NCTAS * 32) g_arrive[i] = 0u;
    if (i == 0) g_phase = 0u;
}

// ---------------------------------------------------------------------------
// Input projection, FFMA2 version: xg[m, n] = sum_k x[m,k]*Xcat[k,n] + b[n]
// 64x64 tiles, BK=16, 256 threads, 4x4 per thread (as 4x2 f32x2 pairs).
// A staged duplicated {v,v} so the broadcast operand is one LDS.128 half.
// Accumulation order identical to scalar version -> bitwise-identical xg.
// ---------------------------------------------------------------------------
__global__ __launch_bounds__(256, 4)
void xproj_kernel(const float* __restrict__ x,
                  const float* __restrict__ X1, const float* __restrict__ X2,
                  const float* __restrict__ X3, const float* __restrict__ X4,
                  const float* __restrict__ b1, const float* __restrict__ b2,
                  const float* __restrict__ b3, const float* __restrict__ b4)
{
    const int n0g  = blockIdx.x * 64;     // global gate-space column
    const int gate = n0g >> 10;
    const int n0   = n0g & 1023;          // column within gate
    const float* __restrict__ Xg = (gate == 0) ? X1 : (gate == 1) ? X2 : (gate == 2) ? X3 : X4;
    const float* __restrict__ bg = (gate == 0) ? b1 : (gate == 1) ? b2 : (gate == 2) ? b3 : b4;

    const int m0 = blockIdx.y * 64;

    __shared__ float Ad[16][128];   // dup pairs: Ad[k][2m],Ad[k][2m+1] = A[m][k]
    __shared__ float Bs[16][64];

    const int tid = threadIdx.x;
    const int tx = tid & 15;        // 4 n-cols each
    const int ty = tid >> 4;        // 4 m-rows each

    unsigned long long acc[4][2];
    #pragma unroll
    for (int r = 0; r < 4; r++) { acc[r][0] = 0ull; acc[r][1] = 0ull; }

    for (int k0 = 0; k0 < IN; k0 += 16) {
        // Stage A 64x16 (duplicated): thread -> row=tid>>2, kq=tid&3
        {
            int row = tid >> 2;
            int kq  = tid & 3;
            float4 v = *(const float4*)(x + (size_t)(m0 + row) * IN + k0 + kq * 4);
            Ad[kq * 4 + 0][2 * row] = v.x;  Ad[kq * 4 + 0][2 * row + 1] = v.x;
            Ad[kq * 4 + 1][2 * row] = v.y;  Ad[kq * 4 + 1][2 * row + 1] = v.y;
            Ad[kq * 4 + 2][2 * row] = v.z;  Ad[kq * 4 + 2][2 * row + 1] = v.z;
            Ad[kq * 4 + 3][2 * row] = v.w;  Ad[kq * 4 + 3][2 * row + 1] = v.w;
        }
        // Stage B 16x64
        {
            int kr = tid >> 4;
            int nq = tid & 15;
            float4 v = *(const float4*)(Xg + (size_t)(k0 + kr) * HD + n0 + nq * 4);
            *(float4*)&Bs[kr][nq * 4] = v;
        }
        __syncthreads();

        #pragma unroll
        for (int k = 0; k < 16; k++) {
            ulonglong2 a01 = *(const ulonglong2*)&Ad[k][2 * (ty * 4)];      // {a0,a0},{a1,a1}
            ulonglong2 a23 = *(const ulonglong2*)&Ad[k][2 * (ty * 4) + 4];  // {a2,a2},{a3,a3}
            ulonglong2 b   = *(const ulonglong2*)&Bs[k][tx * 4];            // {b0,b1},{b2,b3}
            FMA2(acc[0][0], a01.x, b.x); FMA2(acc[0][1], a01.x, b.y);
            FMA2(acc[1][0], a01.y, b.x); FMA2(acc[1][1], a01.y, b.y);
            FMA2(acc[2][0], a23.x, b.x); FMA2(acc[2][1], a23.x, b.y);
            FMA2(acc[3][0], a23.y, b.x); FMA2(acc[3][1], a23.y, b.y);
        }
        __syncthreads();
    }

    #pragma unroll
    for (int r = 0; r < 4; r++) {
        int m = m0 + ty * 4 + r;
        size_t base = (size_t)m * G4 + (size_t)gate * HD + n0 + tx * 4;
        float f0, f1, f2, f3;
        asm("mov.b64 {%0,%1},%2;" : "=f"(f0), "=f"(f1) : "l"(acc[r][0]));
        asm("mov.b64 {%0,%1},%2;" : "=f"(f2), "=f"(f3) : "l"(acc[r][1]));
        g_xg[base + 0] = f0 + bg[n0 + tx * 4 + 0];
        g_xg[base + 1] = f1 + bg[n0 + tx * 4 + 1];
        g_xg[base + 2] = f2 + bg[n0 + tx * 4 + 2];
        g_xg[base + 3] = f3 + bg[n0 + tx * 4 + 3];
    }
}

// ---------------------------------------------------------------------------
// Atomic-free grid barrier. Per-CTA padded flags; CTA0 aggregates with 127
// parallel cg-load pollers; single phase word released by CTA0 thread 0.
// Monotone targets -> no reset, no phase flip.
// ---------------------------------------------------------------------------
__device__ __forceinline__ unsigned ld_cg(const unsigned* p) {
    unsigned v;
    asm volatile("ld.global.cg.u32 %0,[%1];" : "=r"(v) : "l"(p));
    return v;
}
__device__ __forceinline__ void st_cg(unsigned* p, unsigned v) {
    asm volatile("st.global.cg.u32 [%0],%1;" :: "l"(p), "r"(v) : "memory");
}

__device__ __forceinline__ void grid_sync(unsigned target) {
    __syncthreads();
    if (blockIdx.x == 0) {
        const int tid = threadIdx.x;
        if (tid > 0 && tid < NCTAS) {
            while (ld_cg(&g_arrive[tid * 32]) < target) { __nanosleep(32); }
        }
        __syncthreads();
        if (tid == 0) {
            __threadfence();                 // publish CTA0's h stores
            st_cg(&g_phase, target);
        }
    } else {
        if (threadIdx.x == 0) {
            __threadfence();                 // publish this CTA's h stores
            st_cg(&g_arrive[blockIdx.x * 32], target);
            while (ld_cg(&g_phase) < target) { __nanosleep(32); }
        }
        __syncthreads();
    }
}

// ---------------------------------------------------------------------------
// Persistent recurrence kernel: all 512 timesteps in one launch.
// (K-loop identical to Round 5: gate-interleaved B, duplicated-pair A,
//  conflict-free LDS.128, register-only epilogue, c in registers.)
// ---------------------------------------------------------------------------
__global__ void __launch_bounds__(NTHR, 1)
lstm_persistent_kernel(const float* __restrict__ H1, const float* __restrict__ H2,
                       const float* __restrict__ H3, const float* __restrict__ H4,
                       float* __restrict__ out)
{
    extern __shared__ float smem[];
    float* Bs = smem + F_BS;     // [k][jj*4 + gate]
    float* As = smem + F_AS;     // [buf][row][kk dup pairs], stride AS_STRIDE

    const int tid = threadIdx.x;
    const int tx  = tid & 7;     // jj
    const int ty  = tid >> 3;    // 0..15
    const int j0  = blockIdx.x * 8;

    // ---- Load Hcat slice into SMEM once (gate-interleaved columns) ----
    #pragma unroll
    for (int g = 0; g < 4; g++) {
        const float* __restrict__ Hg = (g == 0) ? H1 : (g == 1) ? H2 : (g == 2) ? H3 : H4;
        for (int idx = tid; idx < HD * 8; idx += NTHR) {
            int k  = idx >> 3;
            int jj = idx & 7;
            Bs[k * 32 + jj * 4 + g] = Hg[(size_t)k * HD + j0 + jj];
        }
    }

    // ---- Per-thread epilogue slots: rows {ty + 16*i}, column j0+tx ----
    const float* xptr[4];
    float*       hptr[4];
    float*       optr[4];
    float        c_reg[4] = {0.f, 0.f, 0.f, 0.f};
    #pragma unroll
    for (int i = 0; i < 4; i++) {
        int b = ty + 16 * i;
        int j = j0 + tx;
        xptr[i] = g_xg + (size_t)b * SEQ * G4 + j;
        hptr[i] = g_h + b * HD + j;
        optr[i] = out + (size_t)b * SEQ * HD + j;
    }

    // ---- A-staging slots ----
    int aoff_g[4], aoff_s[4];
    #pragma unroll
    for (int i = 0; i < 4; i++) {
        int q   = tid + NTHR * i;
        int row = q >> 3;
        int kq  = q & 7;
        aoff_g[i] = row * HD + kq * 4;
        aoff_s[i] = row * AS_STRIDE + kq * 8;
    }

    __syncthreads();             // Bs ready

    for (int t = 0; t < SEQ; t++) {
        // ---- Prefetch xg (read-only) — hides under the K loop ----
        float xf[4], xi[4], xc[4], xo[4];
        const size_t toff = (size_t)t * G4;
        #pragma unroll
        for (int i = 0; i < 4; i++) {
            const float* xp = xptr[i] + toff;
            xf[i] = __ldg(xp);
            xi[i] = __ldg(xp + HD);
            xc[i] = __ldg(xp + 2 * HD);
            xo[i] = __ldg(xp + 3 * HD);
        }

        unsigned long long acc[4][2];
        #pragma unroll
        for (int r = 0; r < 4; r++) { acc[r][0] = 0ull; acc[r][1] = 0ull; }

        // ---- Prologue: stage chunk 0 (dup), prefetch chunk 1 ----
        float4 v[4];
        #pragma unroll
        for (int i = 0; i < 4; i++)
            v[i] = __ldcg((const float4*)(g_h + aoff_g[i]));
        #pragma unroll
        for (int i = 0; i < 4; i++) {
            float4 w = v[i];
            *(float4*)&As[aoff_s[i]]     = make_float4(w.x, w.x, w.y, w.y);
            *(float4*)&As[aoff_s[i] + 4] = make_float4(w.z, w.z, w.w, w.w);
        }
        #pragma unroll
        for (int i = 0; i < 4; i++)
            v[i] = __ldcg((const float4*)(g_h + aoff_g[i] + 32));
        __syncthreads();

        for (int ch = 0; ch < 32; ch++) {
            if (ch + 1 < 32) {
                const int nb = ((ch + 1) & 1) * AS_BUF;
                #pragma unroll
                for (int i = 0; i < 4; i++) {
                    float4 w = v[i];
                    *(float4*)&As[nb + aoff_s[i]]     = make_float4(w.x, w.x, w.y, w.y);
                    *(float4*)&As[nb + aoff_s[i] + 4] = make_float4(w.z, w.z, w.w, w.w);
                }
            }
            if (ch + 2 < 32) {
                const int gk = (ch + 2) * 32;
                #pragma unroll
                for (int i = 0; i < 4; i++)
                    v[i] = __ldcg((const float4*)(g_h + aoff_g[i] + gk));
            }

            const float* Bb = Bs + ch * 1024 + tx * 4;
            const char*  Ab = (const char*)(As + (ch & 1) * AS_BUF);
            const ulonglong2* Ar0 = (const ulonglong2*)(Ab + (ty +  0) * 272);
            const ulonglong2* Ar1 = (const ulonglong2*)(Ab + (ty + 16) * 272);
            const ulonglong2* Ar2 = (const ulonglong2*)(Ab + (ty + 32) * 272);
            const ulonglong2* Ar3 = (const ulonglong2*)(Ab + (ty + 48) * 272);

            #pragma unroll
            for (int k2 = 0; k2 < 16; k2++) {
                ulonglong2 b0 = *(const ulonglong2*)(Bb + (2 * k2) * 32);
                ulonglong2 b1 = *(const ulonglong2*)(Bb + (2 * k2 + 1) * 32);

                ulonglong2 a0 = Ar0[k2];
                FMA2(acc[0][0], a0.x, b0.x); FMA2(acc[0][1], a0.x, b0.y);
                FMA2(acc[0][0], a0.y, b1.x); FMA2(acc[0][1], a0.y, b1.y);

                ulonglong2 a1 = Ar1[k2];
                FMA2(acc[1][0], a1.x, b0.x); FMA2(acc[1][1], a1.x, b0.y);
                FMA2(acc[1][0], a1.y, b1.x); FMA2(acc[1][1], a1.y, b1.y);

                ulonglong2 a2 = Ar2[k2];
                FMA2(acc[2][0], a2.x, b0.x); FMA2(acc[2][1], a2.x, b0.y);
                FMA2(acc[2][0], a2.y, b1.x); FMA2(acc[2][1], a2.y, b1.y);

                ulonglong2 a3 = Ar3[k2];
                FMA2(acc[3][0], a3.x, b0.x); FMA2(acc[3][1], a3.x, b0.y);
                FMA2(acc[3][0], a3.y, b1.x); FMA2(acc[3][1], a3.y, b1.y);
            }
            __syncthreads();
        }

        // ---- Epilogue: register-only gates, c/h update, output ----
        #pragma unroll
        for (int i = 0; i < 4; i++) {
            float gf, gi, gc, gg;
            asm("mov.b64 {%0,%1},%2;" : "=f"(gf), "=f"(gi) : "l"(acc[i][0]));
            asm("mov.b64 {%0,%1},%2;" : "=f"(gc), "=f"(gg) : "l"(acc[i][1]));
            gf += xf[i];
            gi += xi[i];
            gc += xc[i];
            gg += xo[i];

            float s1 = 1.0f / (1.0f + expf(-gf));
            float s2 = 1.0f / (1.0f + expf(-gi));
            float t1 = tanhf(gc);
            float s3 = 1.0f / (1.0f + expf(-gg));

            c_reg[i] = c_reg[i] * s1 + s2 * t1;
            float hnew = tanhf(c_reg[i]) * s3;

            *hptr[i] = hnew;
            optr[i][(size_t)t * HD] = hnew;
        }

        // ---- Grid-wide barrier before next step reads updated h ----
        if (t + 1 < SEQ) grid_sync((unsigned)(t + 1));
    }
}

// ---------------------------------------------------------------------------
// Launch
// ---------------------------------------------------------------------------
extern "C" void kernel_launch(void* const* d_in, const int* in_sizes, int n_in,
                              void* d_out, int out_size)
{
    const float* x  = (const float*)d_in[0];
    const float* X1 = (const float*)d_in[1];
    const float* H1 = (const float*)d_in[2];
    const float* b1 = (const float*)d_in[3];
    const float* X2 = (const float*)d_in[4];
    const float* H2 = (const float*)d_in[5];
    const float* b2 = (const float*)d_in[6];
    const float* X3 = (const float*)d_in[7];
    const float* H3 = (const float*)d_in[8];
    const float* b3 = (const float*)d_in[9];
    const float* X4 = (const float*)d_in[10];
    const float* H4 = (const float*)d_in[11];
    const float* b4 = (const float*)d_in[12];
    float* out = (float*)d_out;

    cudaFuncSetAttribute(lstm_persistent_kernel,
                         cudaFuncAttributeMaxDynamicSharedMemorySize, SMEM_TOTAL);

    // Zero recurrent state + barrier flags
    init_state_kernel<<<(BSZ * HD + 255) / 256, 256>>>();

    // Input projection: xg = x @ Xcat + bcat (FFMA2 GEMM)
    dim3 grid_x(G4 / 64, (BSZ * SEQ) / 64, 1);
    xproj_kernel<<<grid_x, 256>>>(x, X1, X2, X3, X4, b1, b2, b3, b4);

    // Persistent recurrence: all 512 steps in one kernel
    lstm_persistent_kernel<<<NCTAS, NTHR, SMEM_TOTAL>>>(H1, H2, H3, H4, out);
}

// round 8
// speedup vs baseline: 1.3257x; 1.3257x over previous
#include <cuda_runtime.h>
#include <math.h>

// Problem constants
constexpr int BSZ = 64;     // batch
constexpr int SEQ = 512;    // sequence length
constexpr int IN  = 512;    // input dim
constexpr int HD  = 1024;   // hidden dim
constexpr int G4  = 4 * HD; // 4096 gate columns

constexpr int NCTAS = 128;  // persistent grid (1 CTA per SM, 148 SMs available)
constexpr int NTHR  = 128;

// Scratch: xg = x @ Xcat + bcat, layout [m = b*SEQ + t][gate*HD + j]
__device__ float g_xg[(size_t)BSZ * SEQ * G4];   // 512 MB
__device__ float g_h[BSZ * HD];
__device__ unsigned g_count;
__device__ unsigned g_phase;

// Dynamic SMEM layout (bytes) -- persistent kernel (PROVEN 14.83ms config):
//   Bs: [1024][32] floats  @ 0        (131072 B)  -- Hcat slice, loaded once
//   As: [2][64][36] floats @ 131072   (18432 B)   -- double-buffered h chunks
//   Gs: [64][36] floats    @ 149504   (9216 B)    -- g tile for epilogue
constexpr int SMEM_BS    = 0;
constexpr int SMEM_AS    = 131072;
constexpr int SMEM_GS    = 149504;
constexpr int SMEM_TOTAL = 149504 + 9216;          // 158720 B

#define FMA2(acc, a, b) asm("fma.rn.f32x2 %0,%1,%2,%0;" : "+l"(acc) : "l"(a), "l"(b))

// ---------------------------------------------------------------------------
// Zero h and barrier state
// ---------------------------------------------------------------------------
__global__ void init_state_kernel() {
    int i = blockIdx.x * blockDim.x + threadIdx.x;
    if (i < BSZ * HD) g_h[i] = 0.0f;
    if (i == 0) { g_count = 0u; g_phase = 0u; }
}

// ---------------------------------------------------------------------------
// ncu alignment dummy: shifts launch numbering so the capture window
// (-s 5 -c 1) lands on the persistent kernel instead of init_state_kernel.
// ---------------------------------------------------------------------------
__global__ void ncu_align_kernel() {}

// ---------------------------------------------------------------------------
// Input projection, FFMA2: xg[m, n] = sum_k x[m,k]*Xcat[k,n] + b[n]
// 64x64 tiles, BK=16, 256 threads, 4 rows x 2 f32x2-col-pairs per thread.
// Per-column accumulation order identical to the scalar version ->
// bitwise-identical xg.
// ---------------------------------------------------------------------------
__global__ __launch_bounds__(256, 4)
void xproj_kernel(const float* __restrict__ x,
                  const float* __restrict__ X1, const float* __restrict__ X2,
                  const float* __restrict__ X3, const float* __restrict__ X4,
                  const float* __restrict__ b1, const float* __restrict__ b2,
                  const float* __restrict__ b3, const float* __restrict__ b4)
{
    const int gate = blockIdx.z;
    const float* __restrict__ Xg = (gate == 0) ? X1 : (gate == 1) ? X2 : (gate == 2) ? X3 : X4;
    const float* __restrict__ bg = (gate == 0) ? b1 : (gate == 1) ? b2 : (gate == 2) ? b3 : b4;

    const int m0 = blockIdx.y * 64;
    const int n0 = blockIdx.x * 64;

    __shared__ float As[16][68];   // [k][m], padded stride 68 (16B-aligned rows)
    __shared__ float Bs[16][64];   // [k][n]

    const int tid = threadIdx.x;
    const int tx = tid & 15;       // 4 n-cols each (2 f32x2 pairs)
    const int ty = tid >> 4;       // 4 m-rows each

    unsigned long long acc[4][2];  // acc[r][0] = cols {0,1}, acc[r][1] = cols {2,3}
    #pragma unroll
    for (int r = 0; r < 4; r++) { acc[r][0] = 0ull; acc[r][1] = 0ull; }

    for (int k0 = 0; k0 < IN; k0 += 16) {
        // Stage A 64x16 transposed: thread -> row=tid>>2, kq=tid&3
        {
            int row = tid >> 2;
            int kq  = tid & 3;
            float4 v = *(const float4*)(x + (size_t)(m0 + row) * IN + k0 + kq * 4);
            As[kq * 4 + 0][row] = v.x;
            As[kq * 4 + 1][row] = v.y;
            As[kq * 4 + 2][row] = v.z;
            As[kq * 4 + 3][row] = v.w;
        }
        // Stage B 16x64, natural layout
        {
            int kr = tid >> 4;
            int nq = tid & 15;
            float4 v = *(const float4*)(Xg + (size_t)(k0 + kr) * HD + n0 + nq * 4);
            *(float4*)&Bs[kr][nq * 4] = v;
        }
        __syncthreads();

        #pragma unroll
        for (int k = 0; k < 16; k++) {
            float4 a4 = *(const float4*)&As[k][ty * 4];          // 4 m-rows
            ulonglong2 b = *(const ulonglong2*)&Bs[k][tx * 4];   // {b0,b1},{b2,b3}

            unsigned long long aa0, aa1, aa2, aa3;
            asm("mov.b64 %0,{%1,%1};" : "=l"(aa0) : "f"(a4.x));
            asm("mov.b64 %0,{%1,%1};" : "=l"(aa1) : "f"(a4.y));
            asm("mov.b64 %0,{%1,%1};" : "=l"(aa2) : "f"(a4.z));
            asm("mov.b64 %0,{%1,%1};" : "=l"(aa3) : "f"(a4.w));

            FMA2(acc[0][0], aa0, b.x); FMA2(acc[0][1], aa0, b.y);
            FMA2(acc[1][0], aa1, b.x); FMA2(acc[1][1], aa1, b.y);
            FMA2(acc[2][0], aa2, b.x); FMA2(acc[2][1], aa2, b.y);
            FMA2(acc[3][0], aa3, b.x); FMA2(acc[3][1], aa3, b.y);
        }
        __syncthreads();
    }

    #pragma unroll
    for (int r = 0; r < 4; r++) {
        int m = m0 + ty * 4 + r;
        size_t base = (size_t)m * G4 + (size_t)gate * HD + n0 + tx * 4;
        float f0, f1, f2, f3;
        asm("mov.b64 {%0,%1},%2;" : "=f"(f0), "=f"(f1) : "l"(acc[r][0]));
        asm("mov.b64 {%0,%1},%2;" : "=f"(f2), "=f"(f3) : "l"(acc[r][1]));
        g_xg[base + 0] = f0 + bg[n0 + tx * 4 + 0];
        g_xg[base + 1] = f1 + bg[n0 + tx * 4 + 1];
        g_xg[base + 2] = f2 + bg[n0 + tx * 4 + 2];
        g_xg[base + 3] = f3 + bg[n0 + tx * 4 + 3];
    }
}

// ---------------------------------------------------------------------------
// Software grid barrier (PROVEN version: atomic count + atomic phase poll)
// ---------------------------------------------------------------------------
__device__ __forceinline__ void grid_sync(unsigned target) {
    __syncthreads();
    if (threadIdx.x == 0) {
        __threadfence();                      // publish h/out stores
        if (atomicAdd(&g_count, 1u) == NCTAS - 1) {
            atomicExch(&g_count, 0u);
            __threadfence();
            atomicExch(&g_phase, target);
        } else {
            while (atomicAdd(&g_phase, 0u) < target) { __nanosleep(64); }
        }
        __threadfence();                      // invalidate L1 so fresh h is read
    }
    __syncthreads();
}

// ---------------------------------------------------------------------------
// Persistent recurrence kernel -- byte-identical to the 14.83ms version.
// Each CTA owns 8 hidden columns (x 4 gates = 32 N-cols) for all 64 batch rows.
//  - Hcat slice cached in SMEM once (128 KB), reused for all steps
//  - c state in registers (exclusive ownership)
//  - h streamed through double-buffered SMEM, LDG prefetch 2 chunks ahead
//  - fma.rn.f32x2 packed math (2 FLOPs/lane/instr)
// ---------------------------------------------------------------------------
__global__ void __launch_bounds__(NTHR, 1)
lstm_persistent_kernel(const float* __restrict__ H1, const float* __restrict__ H2,
                       const float* __restrict__ H3, const float* __restrict__ H4,
                       float* __restrict__ out)
{
    extern __shared__ char smem[];
    float* Bs = (float*)(smem + SMEM_BS);   // [k][c], c = gate*8 + jj, stride 32
    float* As = (float*)(smem + SMEM_AS);   // [buf][row][kk], stride 36, buf stride 2304
    float* Gs = (float*)(smem + SMEM_GS);   // [row][col], stride 36

    const int tid = threadIdx.x;
    const int tx  = tid & 7;                // 4 tile-cols each
    const int ty  = tid >> 3;               // 4 tile-rows each
    const int j0  = blockIdx.x * 8;

    // ---- Load Hcat slice (32 cols x 1024 k) into SMEM once ----
    {
        const int bk  = tid >> 2;           // 0..31
        const int bgt = tid & 3;            // gate
        const float* __restrict__ Hg = (bgt == 0) ? H1 : (bgt == 1) ? H2 : (bgt == 2) ? H3 : H4;
        for (int k0 = 0; k0 < HD; k0 += 32) {
            const float* src = Hg + (size_t)(k0 + bk) * HD + j0;
            float4 v0 = *(const float4*)(src);
            float4 v1 = *(const float4*)(src + 4);
            *(float4*)&Bs[(k0 + bk) * 32 + bgt * 8]     = v0;
            *(float4*)&Bs[(k0 + bk) * 32 + bgt * 8 + 4] = v1;
        }
    }

    const unsigned bs_u = (unsigned)__cvta_generic_to_shared(Bs);

    // ---- Per-thread epilogue slots: 4 (b, j) pairs, fixed for all steps ----
    const float* xptr[4];
    float*       hptr[4];
    float*       optr[4];
    int          goff[4];                   // Gs base offset = b*36 + jj
    float        c_reg[4] = {0.f, 0.f, 0.f, 0.f};
    #pragma unroll
    for (int i = 0; i < 4; i++) {
        int p  = tid + NTHR * i;            // 0..511
        int b  = p >> 3;
        int jj = p & 7;
        int j  = j0 + jj;
        xptr[i] = g_xg + (size_t)b * SEQ * G4 + j;
        hptr[i] = g_h + b * HD + j;
        optr[i] = out + (size_t)b * SEQ * HD + j;
        goff[i] = b * 36 + jj;
    }

    // ---- A-staging slots: 4 float4 per thread per 64x32 chunk ----
    int aoff_g[4];                          // g_h float offset (row*HD + kq*4)
    int aoff_s[4];                          // As float offset (row*36 + kq*4)
    #pragma unroll
    for (int i = 0; i < 4; i++) {
        int q   = tid + NTHR * i;           // 0..511
        int row = q >> 3;                   // 0..63
        int kq  = q & 7;                    // 0..7
        aoff_g[i] = row * HD + kq * 4;
        aoff_s[i] = row * 36 + kq * 4;
    }

    __syncthreads();                        // Bs ready

    for (int t = 0; t < SEQ; t++) {
        // ---- Prefetch xg (DRAM) — hides under the K loop ----
        float xf[4], xi[4], xc[4], xo[4];
        const size_t toff = (size_t)t * G4;
        #pragma unroll
        for (int i = 0; i < 4; i++) {
            const float* xp = xptr[i] + toff;
            xf[i] = __ldg(xp);
            xi[i] = __ldg(xp + HD);
            xc[i] = __ldg(xp + 2 * HD);
            xo[i] = __ldg(xp + 3 * HD);
        }

        unsigned long long acc0[4] = {0ull, 0ull, 0ull, 0ull};  // cols tx*4+0,1
        unsigned long long acc1[4] = {0ull, 0ull, 0ull, 0ull};  // cols tx*4+2,3

        // ---- Prologue: stage chunk 0, prefetch chunk 1 ----
        float4 v[4];
        #pragma unroll
        for (int i = 0; i < 4; i++) v[i] = *(const float4*)(g_h + aoff_g[i]);
        #pragma unroll
        for (int i = 0; i < 4; i++) *(float4*)&As[aoff_s[i]] = v[i];
        #pragma unroll
        for (int i = 0; i < 4; i++) v[i] = *(const float4*)(g_h + aoff_g[i] + 32);
        __syncthreads();

        for (int ch = 0; ch < 32; ch++) {
            // Stage chunk ch+1 into the other buffer (readers done: sync at end of ch-1)
            if (ch + 1 < 32) {
                const int nb = ((ch + 1) & 1) * 2304;
                #pragma unroll
                for (int i = 0; i < 4; i++) *(float4*)&As[nb + aoff_s[i]] = v[i];
            }
            // Prefetch chunk ch+2 from global
            if (ch + 2 < 32) {
                const int gk = (ch + 2) * 32;
                #pragma unroll
                for (int i = 0; i < 4; i++) v[i] = *(const float4*)(g_h + aoff_g[i] + gk);
            }

            const float* Ab = As + (ch & 1) * 2304;
            unsigned baddr = bs_u + (unsigned)(ch * 32 * 32 + tx * 4) * 4u;

            #pragma unroll
            for (int kk = 0; kk < 32; kk++) {
                unsigned long long b01, b23;
                asm volatile("ld.shared.v2.b64 {%0,%1},[%2];"
                             : "=l"(b01), "=l"(b23) : "r"(baddr));
                baddr += 128;

                float a0 = Ab[(ty * 4 + 0) * 36 + kk];
                float a1 = Ab[(ty * 4 + 1) * 36 + kk];
                float a2 = Ab[(ty * 4 + 2) * 36 + kk];
                float a3 = Ab[(ty * 4 + 3) * 36 + kk];

                unsigned long long aa0, aa1, aa2, aa3;
                asm("mov.b64 %0,{%1,%1};" : "=l"(aa0) : "f"(a0));
                asm("mov.b64 %0,{%1,%1};" : "=l"(aa1) : "f"(a1));
                asm("mov.b64 %0,{%1,%1};" : "=l"(aa2) : "f"(a2));
                asm("mov.b64 %0,{%1,%1};" : "=l"(aa3) : "f"(a3));

                asm("fma.rn.f32x2 %0,%1,%2,%0;" : "+l"(acc0[0]) : "l"(aa0), "l"(b01));
                asm("fma.rn.f32x2 %0,%1,%2,%0;" : "+l"(acc1[0]) : "l"(aa0), "l"(b23));
                asm("fma.rn.f32x2 %0,%1,%2,%0;" : "+l"(acc0[1]) : "l"(aa1), "l"(b01));
                asm("fma.rn.f32x2 %0,%1,%2,%0;" : "+l"(acc1[1]) : "l"(aa1), "l"(b23));
                asm("fma.rn.f32x2 %0,%1,%2,%0;" : "+l"(acc0[2]) : "l"(aa2), "l"(b01));
                asm("fma.rn.f32x2 %0,%1,%2,%0;" : "+l"(acc1[2]) : "l"(aa2), "l"(b23));
                asm("fma.rn.f32x2 %0,%1,%2,%0;" : "+l"(acc0[3]) : "l"(aa3), "l"(b01));
                asm("fma.rn.f32x2 %0,%1,%2,%0;" : "+l"(acc1[3]) : "l"(aa3), "l"(b23));
            }
            __syncthreads();
        }

        // ---- Stage g tile into Gs so epilogue threads can gather 4 gates ----
        #pragma unroll
        for (int r = 0; r < 4; r++) {
            float f0, f1, f2, f3;
            asm("mov.b64 {%0,%1},%2;" : "=f"(f0), "=f"(f1) : "l"(acc0[r]));
            asm("mov.b64 {%0,%1},%2;" : "=f"(f2), "=f"(f3) : "l"(acc1[r]));
            float4 g4v = make_float4(f0, f1, f2, f3);
            *(float4*)&Gs[(ty * 4 + r) * 36 + tx * 4] = g4v;
        }
        __syncthreads();

        // ---- Epilogue: gates, c/h update, output ----
        #pragma unroll
        for (int i = 0; i < 4; i++) {
            const int go_ = goff[i];
            float gf = Gs[go_ +  0] + xf[i];
            float gi = Gs[go_ +  8] + xi[i];
            float gc = Gs[go_ + 16] + xc[i];
            float gg = Gs[go_ + 24] + xo[i];

            float s1 = 1.0f / (1.0f + expf(-gf));
            float s2 = 1.0f / (1.0f + expf(-gi));
            float t1 = tanhf(gc);
            float s3 = 1.0f / (1.0f + expf(-gg));

            c_reg[i] = c_reg[i] * s1 + s2 * t1;
            float hnew = tanhf(c_reg[i]) * s3;

            *hptr[i] = hnew;
            optr[i][(size_t)t * HD] = hnew;
        }

        // ---- Grid-wide barrier before next step reads updated h ----
        if (t + 1 < SEQ) grid_sync((unsigned)(t + 1));
    }
}

// ---------------------------------------------------------------------------
// Launch
// ---------------------------------------------------------------------------
extern "C" void kernel_launch(void* const* d_in, const int* in_sizes, int n_in,
                              void* d_out, int out_size)
{
    const float* x  = (const float*)d_in[0];
    const float* X1 = (const float*)d_in[1];
    const float* H1 = (const float*)d_in[2];
    const float* b1 = (const float*)d_in[3];
    const float* X2 = (const float*)d_in[4];
    const float* H2 = (const float*)d_in[5];
    const float* b2 = (const float*)d_in[6];
    const float* X3 = (const float*)d_in[7];
    const float* H3 = (const float*)d_in[8];
    const float* b3 = (const float*)d_in[9];
    const float* X4 = (const float*)d_in[10];
    const float* H4 = (const float*)d_in[11];
    const float* b4 = (const float*)d_in[12];
    float* out = (float*)d_out;

    cudaFuncSetAttribute(lstm_persistent_kernel,
                         cudaFuncAttributeMaxDynamicSharedMemorySize, SMEM_TOTAL);

    // Zero recurrent state + barrier
    init_state_kernel<<<(BSZ * HD + 255) / 256, 256>>>();

    // Input projection: xg = x @ Xcat + bcat (FFMA2 GEMM)
    dim3 grid_x(HD / 64, (BSZ * SEQ) / 64, 4);
    xproj_kernel<<<grid_x, 256>>>(x, X1, X2, X3, X4, b1, b2, b3, b4);

    // ncu alignment: shift capture window toward the persistent kernel
    ncu_align_kernel<<<1, 1>>>();

    // Persistent recurrence: all 512 steps in one kernel
    lstm_persistent_kernel<<<NCTAS, NTHR, SMEM_TOTAL>>>(H1, H2, H3, H4, out);
}

// round 9
// speedup vs baseline: 1.3383x; 1.0095x over previous
#include <cuda_runtime.h>
#include <math.h>

// Problem constants
constexpr int BSZ = 64;     // batch
constexpr int SEQ = 512;    // sequence length
constexpr int IN  = 512;    // input dim
constexpr int HD  = 1024;   // hidden dim
constexpr int G4  = 4 * HD; // 4096 gate columns

constexpr int NCTAS = 128;  // persistent grid (1 CTA per SM, 148 SMs available)
constexpr int NTHR  = 128;

// Scratch: xg = x @ Xcat + bcat, layout [m = b*SEQ + t][gate*HD + j]
__device__ float g_xg[(size_t)BSZ * SEQ * G4];   // 512 MB
__device__ float g_h[BSZ * HD];
__device__ unsigned g_count;
__device__ unsigned g_phase;

// Dynamic SMEM layout (bytes):
//   Bs: [1024][32] floats  @ 0        (131072 B)  -- Hcat slice, loaded once
//   As: [2][64][36] floats @ 131072   (18432 B)   -- double-buffered h chunks
//   Gs: [64][36] floats    @ 149504   (9216 B)    -- g tile for epilogue
constexpr int SMEM_BS    = 0;
constexpr int SMEM_AS    = 131072;
constexpr int SMEM_GS    = 149504;
constexpr int SMEM_TOTAL = 149504 + 9216;          // 158720 B

#define FMA2(acc, a, b) asm("fma.rn.f32x2 %0,%1,%2,%0;" : "+l"(acc) : "l"(a), "l"(b))

// ---------------------------------------------------------------------------
// Zero h and barrier state
// ---------------------------------------------------------------------------
__global__ void init_state_kernel() {
    int i = blockIdx.x * blockDim.x + threadIdx.x;
    if (i < BSZ * HD) g_h[i] = 0.0f;
    if (i == 0) { g_count = 0u; g_phase = 0u; }
}

// ---------------------------------------------------------------------------
// ncu alignment dummy: keeps the capture window on the persistent kernel.
// ---------------------------------------------------------------------------
__global__ void ncu_align_kernel() {}

// ---------------------------------------------------------------------------
// Input projection, FFMA2 (unchanged from Round 7)
// ---------------------------------------------------------------------------
__global__ __launch_bounds__(256, 4)
void xproj_kernel(const float* __restrict__ x,
                  const float* __restrict__ X1, const float* __restrict__ X2,
                  const float* __restrict__ X3, const float* __restrict__ X4,
                  const float* __restrict__ b1, const float* __restrict__ b2,
                  const float* __restrict__ b3, const float* __restrict__ b4)
{
    const int gate = blockIdx.z;
    const float* __restrict__ Xg = (gate == 0) ? X1 : (gate == 1) ? X2 : (gate == 2) ? X3 : X4;
    const float* __restrict__ bg = (gate == 0) ? b1 : (gate == 1) ? b2 : (gate == 2) ? b3 : b4;

    const int m0 = blockIdx.y * 64;
    const int n0 = blockIdx.x * 64;

    __shared__ float As[16][68];   // [k][m], padded stride 68
    __shared__ float Bs[16][64];   // [k][n]

    const int tid = threadIdx.x;
    const int tx = tid & 15;       // 4 n-cols each (2 f32x2 pairs)
    const int ty = tid >> 4;       // 4 m-rows each

    unsigned long long acc[4][2];
    #pragma unroll
    for (int r = 0; r < 4; r++) { acc[r][0] = 0ull; acc[r][1] = 0ull; }

    for (int k0 = 0; k0 < IN; k0 += 16) {
        {
            int row = tid >> 2;
            int kq  = tid & 3;
            float4 v = *(const float4*)(x + (size_t)(m0 + row) * IN + k0 + kq * 4);
            As[kq * 4 + 0][row] = v.x;
            As[kq * 4 + 1][row] = v.y;
            As[kq * 4 + 2][row] = v.z;
            As[kq * 4 + 3][row] = v.w;
        }
        {
            int kr = tid >> 4;
            int nq = tid & 15;
            float4 v = *(const float4*)(Xg + (size_t)(k0 + kr) * HD + n0 + nq * 4);
            *(float4*)&Bs[kr][nq * 4] = v;
        }
        __syncthreads();

        #pragma unroll
        for (int k = 0; k < 16; k++) {
            float4 a4 = *(const float4*)&As[k][ty * 4];
            ulonglong2 b = *(const ulonglong2*)&Bs[k][tx * 4];

            unsigned long long aa0, aa1, aa2, aa3;
            asm("mov.b64 %0,{%1,%1};" : "=l"(aa0) : "f"(a4.x));
            asm("mov.b64 %0,{%1,%1};" : "=l"(aa1) : "f"(a4.y));
            asm("mov.b64 %0,{%1,%1};" : "=l"(aa2) : "f"(a4.z));
            asm("mov.b64 %0,{%1,%1};" : "=l"(aa3) : "f"(a4.w));

            FMA2(acc[0][0], aa0, b.x); FMA2(acc[0][1], aa0, b.y);
            FMA2(acc[1][0], aa1, b.x); FMA2(acc[1][1], aa1, b.y);
            FMA2(acc[2][0], aa2, b.x); FMA2(acc[2][1], aa2, b.y);
            FMA2(acc[3][0], aa3, b.x); FMA2(acc[3][1], aa3, b.y);
        }
        __syncthreads();
    }

    #pragma unroll
    for (int r = 0; r < 4; r++) {
        int m = m0 + ty * 4 + r;
        size_t base = (size_t)m * G4 + (size_t)gate * HD + n0 + tx * 4;
        float f0, f1, f2, f3;
        asm("mov.b64 {%0,%1},%2;" : "=f"(f0), "=f"(f1) : "l"(acc[r][0]));
        asm("mov.b64 {%0,%1},%2;" : "=f"(f2), "=f"(f3) : "l"(acc[r][1]));
        g_xg[base + 0] = f0 + bg[n0 + tx * 4 + 0];
        g_xg[base + 1] = f1 + bg[n0 + tx * 4 + 1];
        g_xg[base + 2] = f2 + bg[n0 + tx * 4 + 2];
        g_xg[base + 3] = f3 + bg[n0 + tx * 4 + 3];
    }
}

// ---------------------------------------------------------------------------
// Software grid barrier (proven version)
// ---------------------------------------------------------------------------
__device__ __forceinline__ void grid_sync(unsigned target) {
    __syncthreads();
    if (threadIdx.x == 0) {
        __threadfence();                      // publish h/out stores
        if (atomicAdd(&g_count, 1u) == NCTAS - 1) {
            atomicExch(&g_count, 0u);
            __threadfence();
            atomicExch(&g_phase, target);
        } else {
            while (atomicAdd(&g_phase, 0u) < target) { __nanosleep(64); }
        }
        __threadfence();                      // invalidate L1 so fresh h is read
    }
    __syncthreads();
}

// ---------------------------------------------------------------------------
// Persistent recurrence kernel. Identical to the 14.6ms version EXCEPT the
// inner-loop A path: thread rows are now {ty, ty+16, ty+32, ty+48}, and A is
// read with one conflict-free LDS.128 per row per 4 kk (banks 4*ty+4*k4,
// distinct within each warp) instead of 16 bank-conflicted scalar LDS.
// ---------------------------------------------------------------------------
__global__ void __launch_bounds__(NTHR, 1)
lstm_persistent_kernel(const float* __restrict__ H1, const float* __restrict__ H2,
                       const float* __restrict__ H3, const float* __restrict__ H4,
                       float* __restrict__ out)
{
    extern __shared__ char smem[];
    float* Bs = (float*)(smem + SMEM_BS);   // [k][c], c = gate*8 + jj, stride 32
    float* As = (float*)(smem + SMEM_AS);   // [buf][row][kk], stride 36
    float* Gs = (float*)(smem + SMEM_GS);   // [row][col], stride 36

    const int tid = threadIdx.x;
    const int tx  = tid & 7;                // 4 tile-cols each
    const int ty  = tid >> 3;               // 0..15
    const int j0  = blockIdx.x * 8;

    // ---- Load Hcat slice (32 cols x 1024 k) into SMEM once ----
    {
        const int bk  = tid >> 2;           // 0..31
        const int bgt = tid & 3;            // gate
        const float* __restrict__ Hg = (bgt == 0) ? H1 : (bgt == 1) ? H2 : (bgt == 2) ? H3 : H4;
        for (int k0 = 0; k0 < HD; k0 += 32) {
            const float* src = Hg + (size_t)(k0 + bk) * HD + j0;
            float4 v0 = *(const float4*)(src);
            float4 v1 = *(const float4*)(src + 4);
            *(float4*)&Bs[(k0 + bk) * 32 + bgt * 8]     = v0;
            *(float4*)&Bs[(k0 + bk) * 32 + bgt * 8 + 4] = v1;
        }
    }

    const unsigned bs_u = (unsigned)__cvta_generic_to_shared(Bs);

    // ---- Per-thread epilogue slots: 4 (b, j) pairs, fixed for all steps ----
    const float* xptr[4];
    float*       hptr[4];
    float*       optr[4];
    int          goff[4];                   // Gs base offset = b*36 + jj
    float        c_reg[4] = {0.f, 0.f, 0.f, 0.f};
    #pragma unroll
    for (int i = 0; i < 4; i++) {
        int p  = tid + NTHR * i;            // 0..511
        int b  = p >> 3;
        int jj = p & 7;
        int j  = j0 + jj;
        xptr[i] = g_xg + (size_t)b * SEQ * G4 + j;
        hptr[i] = g_h + b * HD + j;
        optr[i] = out + (size_t)b * SEQ * HD + j;
        goff[i] = b * 36 + jj;
    }

    // ---- A-staging slots: 4 float4 per thread per 64x32 chunk ----
    int aoff_g[4];                          // g_h float offset (row*HD + kq*4)
    int aoff_s[4];                          // As float offset (row*36 + kq*4)
    #pragma unroll
    for (int i = 0; i < 4; i++) {
        int q   = tid + NTHR * i;           // 0..511
        int row = q >> 3;                   // 0..63
        int kq  = q & 7;                    // 0..7
        aoff_g[i] = row * HD + kq * 4;
        aoff_s[i] = row * 36 + kq * 4;
    }

    __syncthreads();                        // Bs ready

    for (int t = 0; t < SEQ; t++) {
        // ---- Prefetch xg (DRAM) — hides under the K loop ----
        float xf[4], xi[4], xc[4], xo[4];
        const size_t toff = (size_t)t * G4;
        #pragma unroll
        for (int i = 0; i < 4; i++) {
            const float* xp = xptr[i] + toff;
            xf[i] = __ldg(xp);
            xi[i] = __ldg(xp + HD);
            xc[i] = __ldg(xp + 2 * HD);
            xo[i] = __ldg(xp + 3 * HD);
        }

        unsigned long long acc0[4] = {0ull, 0ull, 0ull, 0ull};  // cols tx*4+0,1
        unsigned long long acc1[4] = {0ull, 0ull, 0ull, 0ull};  // cols tx*4+2,3

        // ---- Prologue: stage chunk 0, prefetch chunk 1 ----
        float4 v[4];
        #pragma unroll
        for (int i = 0; i < 4; i++) v[i] = *(const float4*)(g_h + aoff_g[i]);
        #pragma unroll
        for (int i = 0; i < 4; i++) *(float4*)&As[aoff_s[i]] = v[i];
        #pragma unroll
        for (int i = 0; i < 4; i++) v[i] = *(const float4*)(g_h + aoff_g[i] + 32);
        __syncthreads();

        for (int ch = 0; ch < 32; ch++) {
            // Stage chunk ch+1 into the other buffer
            if (ch + 1 < 32) {
                const int nb = ((ch + 1) & 1) * 2304;
                #pragma unroll
                for (int i = 0; i < 4; i++) *(float4*)&As[nb + aoff_s[i]] = v[i];
            }
            // Prefetch chunk ch+2 from global
            if (ch + 2 < 32) {
                const int gk = (ch + 2) * 32;
                #pragma unroll
                for (int i = 0; i < 4; i++) v[i] = *(const float4*)(g_h + aoff_g[i] + gk);
            }

            const float* Ab = As + (ch & 1) * 2304;
            unsigned baddr = bs_u + (unsigned)(ch * 32 * 32 + tx * 4) * 4u;

            #pragma unroll
            for (int k4 = 0; k4 < 8; k4++) {
                // One LDS.128 per row: conflict-free (banks 4*ty + 4*k4)
                float a0v[4], a1v[4], a2v[4], a3v[4];
                *(float4*)a0v = *(const float4*)&Ab[(ty +  0) * 36 + k4 * 4];
                *(float4*)a1v = *(const float4*)&Ab[(ty + 16) * 36 + k4 * 4];
                *(float4*)a2v = *(const float4*)&Ab[(ty + 32) * 36 + k4 * 4];
                *(float4*)a3v = *(const float4*)&Ab[(ty + 48) * 36 + k4 * 4];

                #pragma unroll
                for (int e = 0; e < 4; e++) {
                    unsigned long long b01, b23;
                    asm volatile("ld.shared.v2.b64 {%0,%1},[%2];"
                                 : "=l"(b01), "=l"(b23)
                                 : "r"(baddr + (unsigned)((k4 * 4 + e) * 128)));

                    unsigned long long aa0, aa1, aa2, aa3;
                    asm("mov.b64 %0,{%1,%1};" : "=l"(aa0) : "f"(a0v[e]));
                    asm("mov.b64 %0,{%1,%1};" : "=l"(aa1) : "f"(a1v[e]));
                    asm("mov.b64 %0,{%1,%1};" : "=l"(aa2) : "f"(a2v[e]));
                    asm("mov.b64 %0,{%1,%1};" : "=l"(aa3) : "f"(a3v[e]));

                    FMA2(acc0[0], aa0, b01); FMA2(acc1[0], aa0, b23);
                    FMA2(acc0[1], aa1, b01); FMA2(acc1[1], aa1, b23);
                    FMA2(acc0[2], aa2, b01); FMA2(acc1[2], aa2, b23);
                    FMA2(acc0[3], aa3, b01); FMA2(acc1[3], aa3, b23);
                }
            }
            __syncthreads();
        }

        // ---- Stage g tile into Gs (rows ty + 16r now) ----
        #pragma unroll
        for (int r = 0; r < 4; r++) {
            float f0, f1, f2, f3;
            asm("mov.b64 {%0,%1},%2;" : "=f"(f0), "=f"(f1) : "l"(acc0[r]));
            asm("mov.b64 {%0,%1},%2;" : "=f"(f2), "=f"(f3) : "l"(acc1[r]));
            float4 g4v = make_float4(f0, f1, f2, f3);
            *(float4*)&Gs[(ty + 16 * r) * 36 + tx * 4] = g4v;
        }
        __syncthreads();

        // ---- Epilogue: gates, c/h update, output ----
        #pragma unroll
        for (int i = 0; i < 4; i++) {
            const int go_ = goff[i];
            float gf = Gs[go_ +  0] + xf[i];
            float gi = Gs[go_ +  8] + xi[i];
            float gc = Gs[go_ + 16] + xc[i];
            float gg = Gs[go_ + 24] + xo[i];

            float s1 = 1.0f / (1.0f + expf(-gf));
            float s2 = 1.0f / (1.0f + expf(-gi));
            float t1 = tanhf(gc);
            float s3 = 1.0f / (1.0f + expf(-gg));

            c_reg[i] = c_reg[i] * s1 + s2 * t1;
            float hnew = tanhf(c_reg[i]) * s3;

            *hptr[i] = hnew;
            optr[i][(size_t)t * HD] = hnew;
        }

        // ---- Grid-wide barrier before next step reads updated h ----
        if (t + 1 < SEQ) grid_sync((unsigned)(t + 1));
    }
}

// ---------------------------------------------------------------------------
// Launch
// ---------------------------------------------------------------------------
extern "C" void kernel_launch(void* const* d_in, const int* in_sizes, int n_in,
                              void* d_out, int out_size)
{
    const float* x  = (const float*)d_in[0];
    const float* X1 = (const float*)d_in[1];
    const float* H1 = (const float*)d_in[2];
    const float* b1 = (const float*)d_in[3];
    const float* X2 = (const float*)d_in[4];
    const float* H2 = (const float*)d_in[5];
    const float* b2 = (const float*)d_in[6];
    const float* X3 = (const float*)d_in[7];
    const float* H3 = (const float*)d_in[8];
    const float* b3 = (const float*)d_in[9];
    const float* X4 = (const float*)d_in[10];
    const float* H4 = (const float*)d_in[11];
    const float* b4 = (const float*)d_in[12];
    float* out = (float*)d_out;

    cudaFuncSetAttribute(lstm_persistent_kernel,
                         cudaFuncAttributeMaxDynamicSharedMemorySize, SMEM_TOTAL);

    // Zero recurrent state + barrier
    init_state_kernel<<<(BSZ * HD + 255) / 256, 256>>>();

    // Input projection: xg = x @ Xcat + bcat (FFMA2 GEMM)
    dim3 grid_x(HD / 64, (BSZ * SEQ) / 64, 4);
    xproj_kernel<<<grid_x, 256>>>(x, X1, X2, X3, X4, b1, b2, b3, b4);

    // ncu alignment: keep capture window on the persistent kernel
    ncu_align_kernel<<<1, 1>>>();

    // Persistent recurrence: all 512 steps in one kernel
    lstm_persistent_kernel<<<NCTAS, NTHR, SMEM_TOTAL>>>(H1, H2, H3, H4, out);
}